// round 14
// baseline (speedup 1.0000x reference)
#include <cuda_runtime.h>
#include <cuda_fp16.h>
#include <cstdint>
#include <cstddef>

#define B_    256
#define P_    196
#define E_    2048
#define A_    512
#define MTOT  (B_*P_)      // 50176

// GEMM tiling: 128x128 tile, 256 threads, 2 CTAs/SM, 6-stage swizzled ring,
// persistent CTAs + dynamic tile-stealing (removes wave quantization).
#define MT 128
#define NT 128
#define KC 32
#define NKC (E_/KC)        // 64
#define NSPLIT (A_/NT)     // 4
#define NTILES ((MTOT/MT)*NSPLIT)   // 1568
#define NSTAGE 6
#define TILE_B 8192        // 128 rows x 64B (swizzled, no padding)
#define NPERS  296         // 2 x 148 persistent CTAs

// scratch
__device__ float  g_att2[B_*A_];   // dh@Wd + Wd_b + We_b combined bias
__device__ float  g_att [MTOT];    // logits
__device__ __half g_Bth [A_*E_];   // We transposed to [N][K], fp16 (2MB)
__device__ __half g_ench[(size_t)MTOT*E_];  // enc in fp16 (205MB)
__device__ unsigned g_tile_ctr;    // dynamic tile counter (reset by prep_ench)

// ---------------- helpers ----------------
__device__ __forceinline__ void cp_async16(void* smem_dst, const void* gmem_src){
    unsigned s = (unsigned)__cvta_generic_to_shared(smem_dst);
    asm volatile("cp.async.cg.shared.global [%0], [%1], 16;\n" :: "r"(s), "l"(gmem_src));
}
__device__ __forceinline__ uint32_t packh(float a, float b){
    __half2 h = __floats2half2_rn(a, b);
    return *reinterpret_cast<uint32_t*>(&h);
}
__device__ __forceinline__ void mma_fp16(float c[4], const uint32_t a[4], uint32_t b0, uint32_t b1){
    asm volatile(
        "mma.sync.aligned.m16n8k16.row.col.f32.f16.f16.f32 "
        "{%0,%1,%2,%3}, {%4,%5,%6,%7}, {%8,%9}, {%0,%1,%2,%3};\n"
        : "+f"(c[0]), "+f"(c[1]), "+f"(c[2]), "+f"(c[3])
        : "r"(a[0]), "r"(a[1]), "r"(a[2]), "r"(a[3]), "r"(b0), "r"(b1));
}
__device__ __forceinline__ void ldsm_x4(uint32_t r[4], uint32_t saddr){
    asm volatile("ldmatrix.sync.aligned.m8n8.x4.shared.b16 {%0,%1,%2,%3}, [%4];"
        : "=r"(r[0]), "=r"(r[1]), "=r"(r[2]), "=r"(r[3]) : "r"(saddr));
}
__device__ __forceinline__ uint32_t smem_u32(const void* p){
    return (uint32_t)__cvta_generic_to_shared(p);
}

// ---------------- kernel 0: g_Bth[n][k] = fp16(We[k][n]) ----------------
__global__ void prep_bh(const float* __restrict__ We){
    __shared__ float t[32][33];
    const int k0 = blockIdx.x*32, n0 = blockIdx.y*32;
    const int tx = threadIdx.x, ty = threadIdx.y;   // (32,8)
    #pragma unroll
    for (int i = 0; i < 4; i++)
        t[ty + i*8][tx] = We[(size_t)(k0 + ty + i*8)*A_ + n0 + tx];
    __syncthreads();
    #pragma unroll
    for (int i = 0; i < 4; i++)
        g_Bth[(size_t)(n0 + ty + i*8)*E_ + k0 + tx] = __float2half_rn(t[tx][ty + i*8]);
}

// ---------------- kernel 1: enc -> fp16 (streaming) + zero logits + reset ctr ----------
__global__ void __launch_bounds__(512)
prep_ench(const float* __restrict__ enc){
    const size_t i = ((size_t)blockIdx.x*512 + threadIdx.x)*8;
    const float4 v0 = *(const float4*)(enc + i);
    const float4 v1 = *(const float4*)(enc + i + 4);
    uint4 w;
    w.x = packh(v0.x, v0.y);  w.y = packh(v0.z, v0.w);
    w.z = packh(v1.x, v1.y);  w.w = packh(v1.z, v1.w);
    *(uint4*)(g_ench + i) = w;
    const int j = blockIdx.x*512 + threadIdx.x;
    if (j < MTOT) g_att[j] = 0.f;
    if (j == 0)   g_tile_ctr = 0;
}

// ---------------- kernel 2: att2/bias (64 blocks, 4 batches each) ----------------
__global__ void __launch_bounds__(256)
att2_kernel(const float* __restrict__ dh,  const float* __restrict__ Wd,
            const float* __restrict__ Wdb, const float* __restrict__ Web){
    __shared__ float dh_s[4][512];
    const int tid = threadIdx.x;
    const int bb  = blockIdx.x * 4;
    for (int i = tid; i < 4*512; i += 256)
        dh_s[i >> 9][i & 511] = dh[(size_t)bb*512 + i];
    __syncthreads();

    float acc[4][2];
    {
        const float base0 = Wdb[tid]       + Web[tid];
        const float base1 = Wdb[tid + 256] + Web[tid + 256];
        #pragma unroll
        for (int q = 0; q < 4; q++){ acc[q][0] = base0; acc[q][1] = base1; }
    }
    for (int k = 0; k < 512; k++){
        const float w0 = Wd[(size_t)k*512 + tid];
        const float w1 = Wd[(size_t)k*512 + tid + 256];
        #pragma unroll
        for (int q = 0; q < 4; q++){
            const float d = dh_s[q][k];
            acc[q][0] += d * w0;
            acc[q][1] += d * w1;
        }
    }
    #pragma unroll
    for (int q = 0; q < 4; q++){
        g_att2[(size_t)(bb+q)*512 + tid]       = acc[q][0];
        g_att2[(size_t)(bb+q)*512 + tid + 256] = acc[q][1];
    }
}

// ---------------- kernel 3 (ncu idx 3): persistent fp16 GEMM ----------
// smem: A[6][8KB] | B[6][8KB] | bias[2][128] | wf[128] | satt[128] | tile
#define EX_OFF  (2*NSTAGE*TILE_B)                    // 98304
#define SMEM_BYTES (EX_OFF + (256 + 128 + 128 + 4)*4)

// swizzled byte offset within a tile: row*64 + ((chunk ^ ((row>>1)&3))*16)
#define SWZ(row, chunk) ((row)*64 + ((((chunk) ^ (((row)>>1)&3)) & 3)*16))

#define LF(aa, bb, st, ak, bk) do {                                                 \
    ldsm_x4(aa[0], asb + (uint32_t)((st)*TILE_B) + (ak));                           \
    ldsm_x4(aa[1], asb + (uint32_t)((st)*TILE_B) + 1024 + (ak));                    \
    ldsm_x4(bb[0], bsb + (uint32_t)((st)*TILE_B) + (bk));                           \
    ldsm_x4(bb[1], bsb + (uint32_t)((st)*TILE_B) + 1024 + (bk));                    \
    ldsm_x4(bb[2], bsb + (uint32_t)((st)*TILE_B) + 2048 + (bk));                    \
    ldsm_x4(bb[3], bsb + (uint32_t)((st)*TILE_B) + 3072 + (bk));                    \
} while(0)

#define MMA_SET(aa, bb) do {                                                        \
    _Pragma("unroll")                                                               \
    for (int p = 0; p < 4; p++){                                                    \
        mma_fp16(c[0][2*p+0], aa[0], bb[p][0], bb[p][1]);                           \
        mma_fp16(c[1][2*p+0], aa[1], bb[p][0], bb[p][1]);                           \
        mma_fp16(c[0][2*p+1], aa[0], bb[p][2], bb[p][3]);                           \
        mma_fp16(c[1][2*p+1], aa[1], bb[p][2], bb[p][3]);                           \
    }                                                                               \
} while(0)

#define PREFETCH(ck, st) do {                                                       \
    const size_t ko = (size_t)(ck)*KC;                                              \
    cp_async16(smA + (size_t)((st)*TILE_B) + sw0, Agl + ko);                        \
    cp_async16(smA + (size_t)((st)*TILE_B) + sw1, Agl + ko + 8);                    \
    cp_async16(smB + (size_t)((st)*TILE_B) + sw0, Bgl + ko);                        \
    cp_async16(smB + (size_t)((st)*TILE_B) + sw1, Bgl + ko + 8);                    \
    asm volatile("cp.async.commit_group;\n");                                       \
} while(0)

#define BLK(kb, S0, S1, SP0, SP1) do {                                              \
    asm volatile("cp.async.wait_group 2;\n");                                       \
    __syncthreads();                                                                \
    LF(a0, b0, S0, aoff0, boff0);                                                   \
    PREFETCH((kb)+4, SP0);                                                          \
    LF(a1, b1, S0, aoff1, boff1);  MMA_SET(a0, b0);                                 \
    LF(a0, b0, S1, aoff0, boff0);  MMA_SET(a1, b1);                                 \
    PREFETCH((kb)+5, SP1);                                                          \
    LF(a1, b1, S1, aoff1, boff1);  MMA_SET(a0, b0);                                 \
    MMA_SET(a1, b1);                                                                \
} while(0)

#define BLK_TAIL(S0, S1, WG) do {                                                   \
    asm volatile("cp.async.wait_group " #WG ";\n");                                 \
    __syncthreads();                                                                \
    LF(a0, b0, S0, aoff0, boff0);                                                   \
    LF(a1, b1, S0, aoff1, boff1);  MMA_SET(a0, b0);                                 \
    LF(a0, b0, S1, aoff0, boff0);  MMA_SET(a1, b1);                                 \
    LF(a1, b1, S1, aoff1, boff1);  MMA_SET(a0, b0);                                 \
    MMA_SET(a1, b1);                                                                \
} while(0)

__global__ void __launch_bounds__(256, 2)
gemm_att_kernel(const float* __restrict__ Wf){
    extern __shared__ char smraw[];
    char* smA = smraw;
    char* smB = smraw + NSTAGE*TILE_B;
    float*     bias_s = (float*)(smraw + EX_OFF);            // [2][128]
    float*     wf_s   = bias_s + 256;
    float*     satt   = wf_s + 128;
    unsigned*  s_tile = (unsigned*)(satt + 128);

    const int tid = threadIdx.x;
    const int warp = tid >> 5, lane = tid & 31;
    const int wm = warp >> 1, wn = warp & 1;        // 4x2 warp grid; warp tile 32x64
    const int g = lane >> 2, t = lane & 3;

    // ldmatrix per-lane swizzled offsets (within a tile) — tile-invariant
    const int a_row = lane & 15;
    const int a_cb  = lane >> 4;
    const uint32_t aoff0 = SWZ(a_row, a_cb);
    const uint32_t aoff1 = SWZ(a_row, a_cb + 2);
    const int b_row = (lane & 7) + ((lane >> 4) & 1) * 8;
    const int b_cb  = (lane >> 3) & 1;
    const uint32_t boff0 = SWZ(b_row, b_cb);
    const uint32_t boff1 = SWZ(b_row, b_cb + 2);

    const uint32_t asb = smem_u32(smA) + (uint32_t)(wm*2048);
    const uint32_t bsb = smem_u32(smB) + (uint32_t)(wn*4096);

    const int ld_row = tid >> 1;
    const int ld_c0  = (tid & 1) * 2;
    const uint32_t sw0 = SWZ(ld_row, ld_c0);
    const uint32_t sw1 = SWZ(ld_row, ld_c0 + 1);

    for (;;){
        if (tid == 0) *s_tile = atomicAdd(&g_tile_ctr, 1u);
        __syncthreads();
        const unsigned tile = *s_tile;
        if (tile >= NTILES) break;

        const int m0 = (int)(tile >> 2) * MT;
        const int n0 = (int)(tile & 3)  * NT;
        const int b_first = m0 / P_;

        const __half* Agl = g_ench + (size_t)(m0 + ld_row)*E_ + ld_c0*8;
        const __half* Bgl = g_Bth  + (size_t)(n0 + ld_row)*E_ + ld_c0*8;

        // start the pipeline immediately
        PREFETCH(0, 0);
        PREFETCH(1, 1);
        PREFETCH(2, 2);
        PREFETCH(3, 3);

        // tile prologue (overlaps with in-flight prefetches)
        {
            int j = tid >> 7, c2 = tid & 127;
            int b = b_first + j;
            bias_s[tid] = (b < B_) ? g_att2[(size_t)b*A_ + n0 + c2] : 0.f;
            if (tid < 128){ wf_s[tid] = Wf[n0 + tid]; satt[tid] = 0.f; }
        }

        float c[2][8][4];
        #pragma unroll
        for (int mi = 0; mi < 2; mi++)
            #pragma unroll
            for (int ni = 0; ni < 8; ni++)
                #pragma unroll
                for (int j = 0; j < 4; j++) c[mi][ni][j] = 0.f;

        uint32_t a0[2][4], b0[4][4], a1[2][4], b1[4][4];

        for (int kb = 0; kb < 60; kb += 6){
            BLK(kb,   0, 1, 4, 5);
            BLK(kb+2, 2, 3, 0, 1);
            BLK(kb+4, 4, 5, 2, 3);
        }
        BLK_TAIL(0, 1, 2);
        BLK_TAIL(2, 3, 0);
        __syncthreads();

        // epilogue: h = relu(acc + bias); att += h .* Wf
        float attr[2][2] = {{0.f,0.f},{0.f,0.f}};
        #pragma unroll
        for (int ni = 0; ni < 8; ni++){
            const int cl = wn*64 + ni*8 + 2*t;
            const float w0 = wf_s[cl], w1 = wf_s[cl+1];
            #pragma unroll
            for (int mi = 0; mi < 2; mi++){
                #pragma unroll
                for (int rr = 0; rr < 2; rr++){
                    const int rowg = m0 + wm*32 + mi*16 + g + rr*8;
                    const int rb   = rowg / P_ - b_first;
                    const float bv0 = bias_s[rb*128 + cl];
                    const float bv1 = bias_s[rb*128 + cl + 1];
                    const float h0 = fmaxf(c[mi][ni][rr*2+0] + bv0, 0.f);
                    const float h1 = fmaxf(c[mi][ni][rr*2+1] + bv1, 0.f);
                    attr[mi][rr] += h0*w0 + h1*w1;
                }
            }
        }
        #pragma unroll
        for (int mi = 0; mi < 2; mi++)
            #pragma unroll
            for (int rr = 0; rr < 2; rr++){
                float v = attr[mi][rr];
                v += __shfl_xor_sync(0xffffffffu, v, 1);
                v += __shfl_xor_sync(0xffffffffu, v, 2);
                if (t == 0) atomicAdd(&satt[wm*32 + mi*16 + g + rr*8], v);
            }
        __syncthreads();
        if (tid < 128) atomicAdd(&g_att[m0 + tid], satt[tid]);
        __syncthreads();   // protect satt/bias_s before next tile's prologue
    }
}

// ---------------- kernel 4: fused softmax + awe (one block per batch) ----------------
__global__ void __launch_bounds__(512)
awe_fused(float* __restrict__ alpha_out, float4* __restrict__ out4){
    const int b = blockIdx.x, tid = threadIdx.x;    // 512 threads
    __shared__ float red[512];
    __shared__ float al[P_];

    float v = (tid < P_) ? g_att[b*P_ + tid] : -1e30f;
    red[tid] = v; __syncthreads();
    for (int s = 256; s > 0; s >>= 1){
        if (tid < s) red[tid] = fmaxf(red[tid], red[tid+s]);
        __syncthreads();
    }
    const float mx = red[0]; __syncthreads();
    const float e = (tid < P_) ? expf(v - mx) : 0.f;
    red[tid] = e; __syncthreads();
    for (int s = 256; s > 0; s >>= 1){
        if (tid < s) red[tid] += red[tid+s];
        __syncthreads();
    }
    const float inv = 1.f / red[0];
    if (tid < P_){
        const float a = e * inv;
        alpha_out[b*P_ + tid] = a;
        al[tid] = a;
    }
    __syncthreads();

    float4 acc = make_float4(0.f, 0.f, 0.f, 0.f);
    const uint2* ep = (const uint2*)(g_ench + (size_t)b * P_ * E_) + tid;
    #pragma unroll 4
    for (int p = 0; p < P_; p++){
        const float a = al[p];
        const uint2 u = ep[(size_t)p * (E_/4)];
        const __half2 h0 = *(const __half2*)&u.x;
        const __half2 h1 = *(const __half2*)&u.y;
        acc.x += a * __low2float(h0);  acc.y += a * __high2float(h0);
        acc.z += a * __low2float(h1);  acc.w += a * __high2float(h1);
    }
    out4[(size_t)b * (E_/4) + tid] = acc;
}

// ---------------- launch ----------------
extern "C" void kernel_launch(void* const* d_in, const int* in_sizes, int n_in,
                              void* d_out, int out_size){
    const float* enc  = (const float*)d_in[0];   // (B,P,E)
    const float* dh   = (const float*)d_in[1];   // (1,B,D)
    const float* We_w = (const float*)d_in[2];   // (E,A)
    const float* We_b = (const float*)d_in[3];   // (A)
    const float* Wd_w = (const float*)d_in[4];   // (D,A)
    const float* Wd_b = (const float*)d_in[5];   // (A)
    const float* Wf_w = (const float*)d_in[6];   // (A)
    // d_in[7] = Wf_b: scalar logit shift -> softmax-invariant, outputs don't depend on it.

    float* out       = (float*)d_out;
    float* awe_out   = out;                       // (B,E)
    float* alpha_out = out + (size_t)B_*E_;       // (B,P)

    cudaFuncSetAttribute(gemm_att_kernel, cudaFuncAttributeMaxDynamicSharedMemorySize, SMEM_BYTES);

    prep_bh       <<<dim3(E_/32, A_/32), dim3(32, 8)>>>(We_w);
    prep_ench     <<<(int)((size_t)MTOT*E_/(512*8)), 512>>>(enc);
    att2_kernel   <<<64, 256>>>(dh, Wd_w, Wd_b, We_b);
    gemm_att_kernel<<<NPERS, 256, SMEM_BYTES>>>(Wf_w);   // launch idx 3 -> ncu target
    awe_fused     <<<B_, 512>>>(alpha_out, (float4*)awe_out);
}